// round 4
// baseline (speedup 1.0000x reference)
#include <cuda_runtime.h>
#include <math.h>

#define NN 65536
#define EE 1048576

// ---------------- scratch (device globals; no allocation allowed) ----------------
__device__ float g_h[NN * 64];      // encoded node features, row-major
__device__ float g_Sh[NN * 64];     // sum of h[src] over incoming edges, row-major
__device__ float g_h2[NN * 64];     // updated node features
__device__ float g_misc[NN * 4];    // {sum gx(src), sum gy(src), sum dist, pad}
__device__ int   g_deg[NN];
__device__ int   g_slots[NN * 64];  // incoming src lists, 64 slots per dst
__device__ int   g_flag;            // 0 => edge_index is int64, >0 => int32

__device__ __forceinline__ float gelu_f(float v) { return v * normcdff(v); }

// ---------------- init: zero degrees + dtype-detect flag ----------------
__global__ void k_zero() {
    int i = blockIdx.x * blockDim.x + threadIdx.x;
    if (i < NN) g_deg[i] = 0;
    if (i == 0) g_flag = 0;
}

__global__ void k_detect(const long long* __restrict__ ei) {
    int i = blockIdx.x * blockDim.x + threadIdx.x;
    if (i < 1024) {
        long long v = ei[i];
        if (v < 0 || v >= NN) atomicAdd(&g_flag, 1);
    }
}

// ---------------- encode: h = gelu(cat(x,grid)@W1 + b1) @ W2 + b2 ----------------
__global__ __launch_bounds__(128) void k_encode(
    const float* __restrict__ x, const float* __restrict__ grid,
    const float* __restrict__ W1, const float* __restrict__ b1,
    const float* __restrict__ W2, const float* __restrict__ b2) {
    __shared__ float sW1t[128 * 12];  // [m][f] transposed
    __shared__ float sB1[128];
    __shared__ float sW2[128 * 64];
    __shared__ float sB2[64];
    for (int i = threadIdx.x; i < 12 * 128; i += blockDim.x) {
        int f = i / 128, m = i % 128;
        sW1t[m * 12 + f] = W1[i];
    }
    for (int i = threadIdx.x; i < 128; i += blockDim.x) sB1[i] = b1[i];
    for (int i = threadIdx.x; i < 128 * 64; i += blockDim.x) sW2[i] = W2[i];
    for (int i = threadIdx.x; i < 64; i += blockDim.x) sB2[i] = b2[i];
    __syncthreads();

    int node = blockIdx.x * blockDim.x + threadIdx.x;
    float in[12];
#pragma unroll
    for (int f = 0; f < 10; f++) in[f] = x[node * 10 + f];
    float2 g = ((const float2*)grid)[node];
    in[10] = g.x; in[11] = g.y;

    float acc[64];
#pragma unroll
    for (int o = 0; o < 64; o++) acc[o] = sB2[o];

    for (int m = 0; m < 128; m++) {
        float s = sB1[m];
#pragma unroll
        for (int f = 0; f < 12; f++) s += in[f] * sW1t[m * 12 + f];
        float gl = gelu_f(s);
        const float4* w2r = (const float4*)&sW2[m * 64];
#pragma unroll
        for (int o4 = 0; o4 < 16; o4++) {
            float4 w = w2r[o4];
            acc[o4 * 4 + 0] += gl * w.x;
            acc[o4 * 4 + 1] += gl * w.y;
            acc[o4 * 4 + 2] += gl * w.z;
            acc[o4 * 4 + 3] += gl * w.w;
        }
    }
    float4* hp = (float4*)&g_h[node * 64];
#pragma unroll
    for (int o4 = 0; o4 < 16; o4++)
        hp[o4] = make_float4(acc[o4 * 4], acc[o4 * 4 + 1], acc[o4 * 4 + 2], acc[o4 * 4 + 3]);
}

// ---------------- scatter: bucket edges by destination ----------------
__global__ void k_scatter(const long long* __restrict__ ei64) {
    int e = blockIdx.x * blockDim.x + threadIdx.x;
    if (e >= EE) return;
    int src, dst;
    if (g_flag == 0) {
        src = (int)ei64[e];
        dst = (int)ei64[EE + e];
    } else {
        const int* ei32 = (const int*)ei64;
        src = ei32[e];
        dst = ei32[EE + e];
    }
    int pos = atomicAdd(&g_deg[dst], 1);
    if (pos < 64) g_slots[dst * 64 + pos] = src;
}

// ---------------- aggregate: warp per dst, register accumulation ----------------
__global__ __launch_bounds__(256) void k_aggregate(const float* __restrict__ grid) {
    int gw = (blockIdx.x * blockDim.x + threadIdx.x) >> 5;
    int lane = threadIdx.x & 31;
    if (gw >= NN) return;
    int dst = gw;
    int d = g_deg[dst];
    if (d > 64) d = 64;
    float2 gi = ((const float2*)grid)[dst];
    float ax = 0.f, ay = 0.f, sgx = 0.f, sgy = 0.f, sd = 0.f;
    const int* slot = &g_slots[dst * 64];
    for (int k = 0; k < d; k++) {
        int src = slot[k];                                    // uniform (broadcast)
        float2 hv = *(const float2*)&g_h[src * 64 + 2 * lane]; // gather, L2-resident
        ax += hv.x; ay += hv.y;
        float2 gj = ((const float2*)grid)[src];
        sgx += gj.x; sgy += gj.y;
        float dx = gi.x - gj.x, dy = gi.y - gj.y;
        sd += sqrtf(dx * dx + dy * dy);
    }
    *(float2*)&g_Sh[dst * 64 + 2 * lane] = make_float2(ax, ay);
    if (lane == 0) {
        g_misc[dst * 4 + 0] = sgx;
        g_misc[dst * 4 + 1] = sgy;
        g_misc[dst * 4 + 2] = sd;
        g_misc[dst * 4 + 3] = 0.f;
    }
}

// ---------------- update: h2 = gelu(h@Ww + bw + aggr) (decomposed) ----------------
// aggr[i] = Σdist·Wk[0] + deg·(g_i@Wk[1:3]) + (Σg_j)@Wk[3:5]
//         + deg·(h_i@Wk[5:69]) + (Σh_j)@Wk[69:133] + deg·bk
// dynamic smem layout (floats):
//   sWw[4096] sWxi[4096] sWxj[4096] sGeo[320] sBk[64] sBw[64] stgH[128*17] stgS[128*17]
#define UPD_SMEM_FLOATS (4096 * 3 + 320 + 64 + 64 + 2176 * 2)
__global__ __launch_bounds__(128) void k_update(
    const float* __restrict__ grid,
    const float* __restrict__ Wk, const float* __restrict__ bk,
    const float* __restrict__ Ww, const float* __restrict__ bw) {
    extern __shared__ float sm[];
    float* sWw  = sm;
    float* sWxi = sm + 4096;
    float* sWxj = sm + 8192;
    float* sGeo = sm + 12288;
    float* sBk  = sm + 12608;
    float* sBw  = sm + 12672;
    float* stgH = sm + 12736;
    float* stgS = sm + 14912;

    for (int i = threadIdx.x; i < 4096; i += blockDim.x) {
        sWw[i]  = Ww[i];
        sWxi[i] = Wk[5 * 64 + i];   // rows 5..68   (x_i block)
        sWxj[i] = Wk[69 * 64 + i];  // rows 69..132 (x_j block)
    }
    for (int i = threadIdx.x; i < 320; i += blockDim.x) sGeo[i] = Wk[i];  // rows 0..4
    for (int i = threadIdx.x; i < 64; i += blockDim.x) { sBk[i] = bk[i]; sBw[i] = bw[i]; }
    __syncthreads();

    int base = blockIdx.x * 128;
    int node = base + threadIdx.x;
    float fdeg = (float)g_deg[node];
    float4 misc = *(const float4*)&g_misc[node * 4];  // x=Σgx, y=Σgy, z=Σdist
    float2 gi = ((const float2*)grid)[node];

    float acc[64];
#pragma unroll
    for (int o = 0; o < 64; o++)
        acc[o] = sBw[o] + fdeg * sBk[o]
               + misc.z * sGeo[o]
               + fdeg * gi.x * sGeo[64 + o] + fdeg * gi.y * sGeo[128 + o]   // FIX: deg factor on g_i
               + misc.x * sGeo[192 + o] + misc.y * sGeo[256 + o];

    for (int c = 0; c < 4; c++) {
        __syncthreads();
        for (int q = threadIdx.x; q < 2048; q += 128) {
            int r = q >> 4, jj = q & 15;
            int ga = (base + r) * 64 + c * 16 + jj;
            stgH[r * 17 + jj] = g_h[ga];
            stgS[r * 17 + jj] = g_Sh[ga];
        }
        __syncthreads();
        for (int jj = 0; jj < 16; jj++) {
            float hv = stgH[threadIdx.x * 17 + jj];
            float sv = stgS[threadIdx.x * 17 + jj];
            float dv = fdeg * hv;
            int j = c * 16 + jj;
            const float4* wW = (const float4*)&sWw[j * 64];
            const float4* wI = (const float4*)&sWxi[j * 64];
            const float4* wJ = (const float4*)&sWxj[j * 64];
#pragma unroll
            for (int o4 = 0; o4 < 16; o4++) {
                float4 a = wW[o4], b = wI[o4], cc = wJ[o4];
                acc[o4 * 4 + 0] += hv * a.x + dv * b.x + sv * cc.x;
                acc[o4 * 4 + 1] += hv * a.y + dv * b.y + sv * cc.y;
                acc[o4 * 4 + 2] += hv * a.z + dv * b.z + sv * cc.z;
                acc[o4 * 4 + 3] += hv * a.w + dv * b.w + sv * cc.w;
            }
        }
    }
    float4* hp = (float4*)&g_h2[node * 64];
#pragma unroll
    for (int o4 = 0; o4 < 16; o4++)
        hp[o4] = make_float4(gelu_f(acc[o4 * 4]), gelu_f(acc[o4 * 4 + 1]),
                             gelu_f(acc[o4 * 4 + 2]), gelu_f(acc[o4 * 4 + 3]));
}

// ---------------- decode: out = gelu(h2@Wd1 + b1) @ Wd2 + b2 ----------------
__global__ __launch_bounds__(128) void k_decode(
    const float* __restrict__ Wd1, const float* __restrict__ bd1,
    const float* __restrict__ Wd2, const float* __restrict__ bd2,
    float* __restrict__ out) {
    __shared__ float sW[128 * 68];  // transposed [m][j], padded stride 68 (16B-aligned rows)
    __shared__ float sB1[128];
    __shared__ float sW2[128];
    __shared__ float stg[128 * 17];
    for (int i = threadIdx.x; i < 64 * 128; i += blockDim.x) {
        int j = i / 128, m = i % 128;
        sW[m * 68 + j] = Wd1[i];
    }
    for (int i = threadIdx.x; i < 128; i += blockDim.x) { sB1[i] = bd1[i]; sW2[i] = Wd2[i]; }
    __syncthreads();

    int base = blockIdx.x * 128;
    float h2[64];
#pragma unroll
    for (int c = 0; c < 4; c++) {
        __syncthreads();
        for (int q = threadIdx.x; q < 2048; q += 128) {
            int r = q >> 4, jj = q & 15;
            stg[r * 17 + jj] = g_h2[(base + r) * 64 + c * 16 + jj];
        }
        __syncthreads();
#pragma unroll
        for (int jj = 0; jj < 16; jj++) h2[c * 16 + jj] = stg[threadIdx.x * 17 + jj];
    }

    float o = 0.f;
    for (int m = 0; m < 128; m++) {
        float s = sB1[m];
        const float4* w = (const float4*)&sW[m * 68];
#pragma unroll
        for (int j4 = 0; j4 < 16; j4++) {
            float4 ww = w[j4];
            s += h2[j4 * 4 + 0] * ww.x + h2[j4 * 4 + 1] * ww.y +
                 h2[j4 * 4 + 2] * ww.z + h2[j4 * 4 + 3] * ww.w;
        }
        o += gelu_f(s) * sW2[m];
    }
    out[base + threadIdx.x] = o + bd2[0];
}

// ---------------- launch ----------------
extern "C" void kernel_launch(void* const* d_in, const int* in_sizes, int n_in,
                              void* d_out, int out_size) {
    const float*     x    = (const float*)d_in[0];
    const float*     grid = (const float*)d_in[1];
    const long long* ei   = (const long long*)d_in[2];  // may really be int32; detected
    const float* W1  = (const float*)d_in[3];
    const float* b1  = (const float*)d_in[4];
    const float* W2  = (const float*)d_in[5];
    const float* b2  = (const float*)d_in[6];
    const float* Wk  = (const float*)d_in[7];
    const float* bk  = (const float*)d_in[8];
    const float* Ww  = (const float*)d_in[9];
    const float* bw  = (const float*)d_in[10];
    const float* Wd1 = (const float*)d_in[11];
    const float* bd1 = (const float*)d_in[12];
    const float* Wd2 = (const float*)d_in[13];
    const float* bd2 = (const float*)d_in[14];
    float* out = (float*)d_out;

    cudaFuncSetAttribute(k_update, cudaFuncAttributeMaxDynamicSharedMemorySize,
                         UPD_SMEM_FLOATS * (int)sizeof(float));

    k_zero<<<NN / 256, 256>>>();
    k_detect<<<4, 256>>>(ei);
    k_encode<<<NN / 128, 128>>>(x, grid, W1, b1, W2, b2);
    k_scatter<<<EE / 256, 256>>>(ei);
    k_aggregate<<<(NN * 32) / 256, 256>>>(grid);
    k_update<<<NN / 128, 128, UPD_SMEM_FLOATS * (int)sizeof(float)>>>(grid, Wk, bk, Ww, bw);
    k_decode<<<NN / 128, 128>>>(Wd1, bd1, Wd2, bd2, out);
}